// round 1
// baseline (speedup 1.0000x reference)
#include <cuda_runtime.h>
#include <cuda_bf16.h>
#include <cstdint>

#define CB 64
#define CS 2048
#define CT 256
#define NROWS_REG 64
#define NROWS_SM  192
#define PITCH     196   // floats per smem column (192 rows + 4 pad) -> conflict-free LDS.128

__device__ float g_logz[CB];
__device__ float g_score[CB];

__device__ __forceinline__ float warp_max(float v) {
#pragma unroll
    for (int o = 16; o > 0; o >>= 1)
        v = fmaxf(v, __shfl_xor_sync(0xffffffffu, v, o));
    return v;
}
__device__ __forceinline__ float warp_sum(float v) {
#pragma unroll
    for (int o = 16; o > 0; o >>= 1)
        v += __shfl_xor_sync(0xffffffffu, v, o);
    return v;
}

// ---------------------------------------------------------------------------
// Forward algorithm: one CTA per batch, thread j owns tag-column j.
// alpha_new[j] = m + log( sum_i exp(alpha[i]-m) * M[i][j] ) + emit[t][j]
// M rows 0..63 live in registers (per-thread column slice), rows 64..255 in
// smem fp32 column-major. p broadcast via float4 from smem.
// ---------------------------------------------------------------------------
__global__ void __launch_bounds__(CT, 1)
crf_forward(const float* __restrict__ emissions,
            const float* __restrict__ trans,
            const float* __restrict__ start_t,
            const float* __restrict__ end_t)
{
    extern __shared__ float smem[];
    float* Mc   = smem;                 // [CT][PITCH] col-major: col j at Mc + j*PITCH
    float* sp   = smem + CT * PITCH;    // p[256] (16B aligned: CT*PITCH*4 % 16 == 0)
    float* wred = sp + CT;              // 8 warp partials

    const int j = threadIdx.x;
    const int b = blockIdx.x;

    // Build M = exp(trans). Coalesced global reads (thread j -> column j).
    float Mreg[NROWS_REG];
#pragma unroll
    for (int i = 0; i < NROWS_REG; i++)
        Mreg[i] = __expf(trans[i * CT + j]);
    for (int r = 0; r < NROWS_SM; r++)
        Mc[j * PITCH + r] = __expf(trans[(NROWS_REG + r) * CT + j]);
    __syncthreads();

    const float* em = emissions + (size_t)b * CS * CT;
    float alpha = start_t[j] + em[j];   // t = 0

    for (int t = 1; t < CS; t++) {
        // Prefetch this step's emission early; consumed ~1k cycles later.
        float e = __ldg(em + (size_t)t * CT + j);

        // block max of alpha
        float wm = warp_max(alpha);
        if ((j & 31) == 0) wred[j >> 5] = wm;
        __syncthreads();
        float m = wred[0];
#pragma unroll
        for (int w = 1; w < 8; w++) m = fmaxf(m, wred[w]);

        sp[j] = __expf(alpha - m);
        __syncthreads();

        // dot(p, M[:, j])
        const float4* p4  = (const float4*)sp;
        const float4* mc4 = (const float4*)(Mc + j * PITCH);
        float s0 = 0.f, s1 = 0.f, s2 = 0.f, s3 = 0.f;
#pragma unroll
        for (int k = 0; k < NROWS_REG / 4; k++) {
            float4 pv = p4[k];
            s0 += pv.x * Mreg[4 * k + 0];
            s1 += pv.y * Mreg[4 * k + 1];
            s2 += pv.z * Mreg[4 * k + 2];
            s3 += pv.w * Mreg[4 * k + 3];
        }
#pragma unroll
        for (int k = 0; k < NROWS_SM / 4; k++) {
            float4 pv = p4[NROWS_REG / 4 + k];
            float4 mv = mc4[k];
            s0 += pv.x * mv.x;
            s1 += pv.y * mv.y;
            s2 += pv.z * mv.z;
            s3 += pv.w * mv.w;
        }
        float sum = (s0 + s1) + (s2 + s3);
        alpha = m + __logf(sum) + e;
    }

    // log_z = logsumexp_j(alpha[j] + end_t[j])
    float v = alpha + end_t[j];
    float wm = warp_max(v);
    if ((j & 31) == 0) wred[j >> 5] = wm;
    __syncthreads();
    float m = wred[0];
#pragma unroll
    for (int w = 1; w < 8; w++) m = fmaxf(m, wred[w]);
    float pe = warp_sum(__expf(v - m));
    __syncthreads();                    // wred reuse
    if ((j & 31) == 0) wred[j >> 5] = pe;
    __syncthreads();
    if (j == 0) {
        float tot = 0.f;
#pragma unroll
        for (int w = 0; w < 8; w++) tot += wred[w];
        g_logz[b] = m + __logf(tot);
    }
}

// ---------------------------------------------------------------------------
// Gold-path score: one CTA per batch.
// ---------------------------------------------------------------------------
__global__ void __launch_bounds__(256)
crf_score(const float* __restrict__ emissions,
          const int*   __restrict__ tags,
          const int*   __restrict__ mask,
          const float* __restrict__ trans,
          const float* __restrict__ start_t,
          const float* __restrict__ end_t)
{
    __shared__ float fred[8];
    __shared__ int   ired[8];
    const int b   = blockIdx.x;
    const int tid = threadIdx.x;
    const int*   tg = tags + b * CS;
    const int*   mk = mask + b * CS;
    const float* em = emissions + (size_t)b * CS * CT;

    float part = 0.f;
    int   msum = 0;
    for (int t = tid; t < CS; t += 256) {
        msum += mk[t];
        if (t >= 1 && mk[t]) {
            int a = tg[t], p = tg[t - 1];
            part += trans[a * CT + p] + em[(size_t)t * CT + a];
        }
    }
    float wsum = warp_sum(part);
#pragma unroll
    for (int o = 16; o > 0; o >>= 1)
        msum += __shfl_xor_sync(0xffffffffu, msum, o);
    if ((tid & 31) == 0) { fred[tid >> 5] = wsum; ired[tid >> 5] = msum; }
    __syncthreads();
    if (tid == 0) {
        float tot = 0.f; int mt = 0;
#pragma unroll
        for (int w = 0; w < 8; w++) { tot += fred[w]; mt += ired[w]; }
        int t0   = tg[0];
        int last = tg[mt - 1];          // seq_end = mask.sum() - 1
        g_score[b] = tot + start_t[t0] + em[t0] + end_t[last];
    }
}

// ---------------------------------------------------------------------------
// Final: mean over batch of (score - logz).
// ---------------------------------------------------------------------------
__global__ void crf_final(float* __restrict__ out)
{
    __shared__ float sred[2];
    int t = threadIdx.x;                // 64 threads
    float v = g_score[t] - g_logz[t];
    float w = warp_sum(v);
    if ((t & 31) == 0) sred[t >> 5] = w;
    __syncthreads();
    if (t == 0) out[0] = (sred[0] + sred[1]) * (1.0f / CB);
}

extern "C" void kernel_launch(void* const* d_in, const int* in_sizes, int n_in,
                              void* d_out, int out_size)
{
    const float* emissions = (const float*)d_in[0];
    const int*   tags      = (const int*)d_in[1];
    const int*   mask      = (const int*)d_in[2];
    const float* trans     = (const float*)d_in[3];
    const float* start_t   = (const float*)d_in[4];
    const float* end_t     = (const float*)d_in[5];
    float* out = (float*)d_out;

    size_t smem = (size_t)(CT * PITCH + CT + 16) * sizeof(float);  // ~202 KB
    cudaFuncSetAttribute(crf_forward, cudaFuncAttributeMaxDynamicSharedMemorySize,
                         (int)smem);

    crf_forward<<<CB, CT, smem>>>(emissions, trans, start_t, end_t);
    crf_score<<<CB, 256>>>(emissions, tags, mask, trans, start_t, end_t);
    crf_final<<<1, 64>>>(out);
}

// round 2
// speedup vs baseline: 2.8957x; 2.8957x over previous
#include <cuda_runtime.h>
#include <cuda_fp16.h>
#include <cstdint>
#include <cstring>

#define CB 64
#define CS 2048
#define CT 256
#define GSH 9   // expected log2 growth per step (renormalization bias)

__device__ float g_logz[CB];
__device__ float g_score[CB];

__device__ __forceinline__ float warp_max(float v) {
#pragma unroll
    for (int o = 16; o > 0; o >>= 1)
        v = fmaxf(v, __shfl_xor_sync(0xffffffffu, v, o));
    return v;
}
__device__ __forceinline__ float warp_sum(float v) {
#pragma unroll
    for (int o = 16; o > 0; o >>= 1)
        v += __shfl_xor_sync(0xffffffffu, v, o);
    return v;
}
__device__ __forceinline__ __half2 u2h2(unsigned u) {
    __half2 h; memcpy(&h, &u, 4); return h;
}

// ---------------------------------------------------------------------------
// Forward algorithm in probability space with power-of-2 renormalization.
// One CTA per batch; thread j owns column j. M = exp(trans) lives ENTIRELY in
// registers as 128 half2 (row-pairs). Per step:
//   s_j = sum_i p_i * M[i][j]        (HFMA2, 8 independent half2 accumulators)
//   A_j = s_j * exp(e_j) * 2^-(k+G)  (k = exponent of sampled max of p,
//                                     identical on all threads -> no comm)
//   p[j] = fp16(A_j); one __syncthreads (double-buffered p).
// log Z = m0 + ksum*ln2 + log(sum_j A_j * exp(end_j)).
// ---------------------------------------------------------------------------
__global__ void __launch_bounds__(CT, 1)
crf_forward(const float* __restrict__ emissions,
            const float* __restrict__ trans,
            const float* __restrict__ start_t,
            const float* __restrict__ end_t)
{
    __shared__ __align__(16) __half pbuf[2][CT];
    __shared__ float wred[8];

    const int j = threadIdx.x;
    const int b = blockIdx.x;

    // Build M = exp(trans) fp16, column j, packed row-pairs (2r, 2r+1).
    __half2 M[128];
#pragma unroll
    for (int r = 0; r < 128; r++) {
        float a0 = __expf(trans[(2 * r)     * CT + j]);
        float a1 = __expf(trans[(2 * r + 1) * CT + j]);
        M[r] = __floats2half2_rn(a0, a1);
    }

    const float* em = emissions + (size_t)b * CS * CT;
    float alpha0 = start_t[j] + em[j];

    // One-time block max for the initial exponentiation.
    float wm = warp_max(alpha0);
    if ((j & 31) == 0) wred[j >> 5] = wm;
    __syncthreads();
    float m0 = wred[0];
#pragma unroll
    for (int w = 1; w < 8; w++) m0 = fmaxf(m0, wred[w]);

    float A = __expf(alpha0 - m0);
    int ksum = 0;

    pbuf[0][j] = __float2half_rn(A);
    float e_next = em[CT + j];
    __syncthreads();

    for (int t = 1; t < CS; t++) {
        const uint4* p4 = (const uint4*)pbuf[(t - 1) & 1];
        float e = e_next;
        int tn = (t + 1 < CS) ? (t + 1) : (CS - 1);
        e_next = __ldg(em + (size_t)tn * CT + j);   // prefetch next emission

        __half2 z = __float2half2_rn(0.f);
        __half2 acc0 = z, acc1 = z, acc2 = z, acc3 = z;
        __half2 acc4 = z, acc5 = z, acc6 = z, acc7 = z;
        __half2 mx = z;

#pragma unroll
        for (int c = 0; c < 32; c++) {
            uint4 v = p4[c];                 // broadcast: 1 wavefront/warp
            __half2 h0 = u2h2(v.x);
            __half2 h1 = u2h2(v.y);
            __half2 h2 = u2h2(v.z);
            __half2 h3 = u2h2(v.w);
            mx = __hmax2(mx, h0);            // sampled max (64 of 256 values)
            if (c & 1) {
                acc4 = __hfma2(M[4 * c + 0], h0, acc4);
                acc5 = __hfma2(M[4 * c + 1], h1, acc5);
                acc6 = __hfma2(M[4 * c + 2], h2, acc6);
                acc7 = __hfma2(M[4 * c + 3], h3, acc7);
            } else {
                acc0 = __hfma2(M[4 * c + 0], h0, acc0);
                acc1 = __hfma2(M[4 * c + 1], h1, acc1);
                acc2 = __hfma2(M[4 * c + 2], h2, acc2);
                acc3 = __hfma2(M[4 * c + 3], h3, acc3);
            }
        }

        // fp32 combine of the 16 fp16 partials
        float2 f0 = __half22float2(acc0), f1 = __half22float2(acc1);
        float2 f2 = __half22float2(acc2), f3 = __half22float2(acc3);
        float2 f4 = __half22float2(acc4), f5 = __half22float2(acc5);
        float2 f6 = __half22float2(acc6), f7 = __half22float2(acc7);
        float s = ((f0.x + f0.y) + (f1.x + f1.y)) + ((f2.x + f2.y) + (f3.x + f3.y))
                + ((f4.x + f4.y) + (f5.x + f5.y)) + ((f6.x + f6.y) + (f7.x + f7.y));

        // shared exponent from sampled max of p (identical on every thread)
        __half hmx = __hmax(__low2half(mx), __high2half(mx));
        int k = (int)((__half_as_ushort(hmx) >> 10) & 0x1F) - 15;
        float scale = __int_as_float((127 - k - GSH) << 23);
        ksum += k + GSH;

        A = __expf(e) * (s * scale);
        pbuf[t & 1][j] = __float2half_rn(A);
        __syncthreads();
    }

    // log_z = m0 + ksum*ln2 + log(sum_j A_j * exp(end_j))  (A already normalized)
    float v = A * __expf(end_t[j]);
    float ws = warp_sum(v);
    if ((j & 31) == 0) wred[j >> 5] = ws;
    __syncthreads();
    if (j == 0) {
        float tot = 0.f;
#pragma unroll
        for (int w = 0; w < 8; w++) tot += wred[w];
        g_logz[b] = m0 + (float)ksum * 0.693147180559945f + logf(tot);
    }
}

// ---------------------------------------------------------------------------
// Gold-path score: one CTA per batch.
// ---------------------------------------------------------------------------
__global__ void __launch_bounds__(256)
crf_score(const float* __restrict__ emissions,
          const int*   __restrict__ tags,
          const int*   __restrict__ mask,
          const float* __restrict__ trans,
          const float* __restrict__ start_t,
          const float* __restrict__ end_t)
{
    __shared__ float fred[8];
    __shared__ int   ired[8];
    const int b   = blockIdx.x;
    const int tid = threadIdx.x;
    const int*   tg = tags + b * CS;
    const int*   mk = mask + b * CS;
    const float* em = emissions + (size_t)b * CS * CT;

    float part = 0.f;
    int   msum = 0;
    for (int t = tid; t < CS; t += 256) {
        msum += mk[t];
        if (t >= 1 && mk[t]) {
            int a = tg[t], p = tg[t - 1];
            part += trans[a * CT + p] + em[(size_t)t * CT + a];
        }
    }
    float wsum = warp_sum(part);
#pragma unroll
    for (int o = 16; o > 0; o >>= 1)
        msum += __shfl_xor_sync(0xffffffffu, msum, o);
    if ((tid & 31) == 0) { fred[tid >> 5] = wsum; ired[tid >> 5] = msum; }
    __syncthreads();
    if (tid == 0) {
        float tot = 0.f; int mt = 0;
#pragma unroll
        for (int w = 0; w < 8; w++) { tot += fred[w]; mt += ired[w]; }
        int t0   = tg[0];
        int last = tg[mt - 1];          // seq_end = mask.sum() - 1
        g_score[b] = tot + start_t[t0] + em[t0] + end_t[last];
    }
}

// ---------------------------------------------------------------------------
// Final: mean over batch of (score - logz).
// ---------------------------------------------------------------------------
__global__ void crf_final(float* __restrict__ out)
{
    __shared__ float sred[2];
    int t = threadIdx.x;                // 64 threads
    float v = g_score[t] - g_logz[t];
    float w = warp_sum(v);
    if ((t & 31) == 0) sred[t >> 5] = w;
    __syncthreads();
    if (t == 0) out[0] = (sred[0] + sred[1]) * (1.0f / CB);
}

extern "C" void kernel_launch(void* const* d_in, const int* in_sizes, int n_in,
                              void* d_out, int out_size)
{
    const float* emissions = (const float*)d_in[0];
    const int*   tags      = (const int*)d_in[1];
    const int*   mask      = (const int*)d_in[2];
    const float* trans     = (const float*)d_in[3];
    const float* start_t   = (const float*)d_in[4];
    const float* end_t     = (const float*)d_in[5];
    float* out = (float*)d_out;

    crf_forward<<<CB, CT>>>(emissions, trans, start_t, end_t);
    crf_score<<<CB, 256>>>(emissions, tags, mask, trans, start_t, end_t);
    crf_final<<<1, 64>>>(out);
}